// round 9
// baseline (speedup 1.0000x reference)
#include <cuda_runtime.h>
#include <math.h>

#define B 8
#define C 256
#define H 128
#define W 128
#define OH 65
#define OW 65
#define HW (H*W)          // 16384
#define OHW (OH*OW)       // 4225

// ---------------------------------------------------------------------------
// Fused kernel: block = (b, oy). 416 threads (13 warps).
//   Pass 1 (t<384): 3 input rows x 128 cols, channel-walk sum-of-squares
//   Softmax (t<65): 9 weights per output pixel -> smem
//   Pass 2 (t<390): 6 channel-groups x 65 ox, weighted sum from L2-hot rows
// Pads exact: pad-norm = 0 in softmax; pad-x removed by zeroing its weight.
// ---------------------------------------------------------------------------
__global__ __launch_bounds__(416, 3) void fused_kernel(const float* __restrict__ x,
                                                       float* __restrict__ out) {
    __shared__ float s_n[3][136];    // norms, index = global_col + 2
    __shared__ float s_w[65][12];    // 9 weights per ox (stride 12)

    int bid = blockIdx.x;
    int oy  = bid % OH;
    int b   = bid / OH;
    int iy0 = 2 * oy - 2;
    int t   = threadIdx.x;

    // ---- Pass 1: channel sum-of-squares for 3x128 positions ----
    if (t < 384) {
        int row = t >> 7;            // 0..2
        int col = t & 127;           // 0..127
        int iy  = iy0 + row;
        bool rv = (unsigned)iy < (unsigned)H;
        int iyc = iy < 0 ? 0 : (iy >= H ? H - 1 : iy);
        const float* p = x + (size_t)b * C * HW + (size_t)iyc * W + col;

        float s0 = 0.f, s1 = 0.f;
        #pragma unroll 8
        for (int c = 0; c < C; c += 2) {
            float v0 = p[(size_t)c * HW];
            float v1 = p[(size_t)(c + 1) * HW];
            s0 = fmaf(v0, v0, s0);
            s1 = fmaf(v1, v1, s1);
        }
        s_n[row][col + 2] = rv ? sqrtf(s0 + s1) : 0.f;
        if (col < 2)    s_n[row][col] = 0.f;        // global cols -2,-1
        if (col >= 126) s_n[row][col + 4] = 0.f;    // global cols 128,129
    }
    __syncthreads();

    // ---- Softmax over the 3x3 norm window ----
    if (t < 65) {
        int ox = t;
        float v[9];
        #pragma unroll
        for (int i = 0; i < 3; i++)
            #pragma unroll
            for (int j = 0; j < 3; j++)
                v[i * 3 + j] = s_n[i][2 * ox + j];   // global col 2ox-2+j

        float m = v[0];
        #pragma unroll
        for (int k = 1; k < 9; k++) m = fmaxf(m, v[k]);
        float e[9], sum = 0.f;
        #pragma unroll
        for (int k = 0; k < 9; k++) { e[k] = expf(v[k] - m); sum += e[k]; }
        float inv = 1.f / sum;
        #pragma unroll
        for (int k = 0; k < 9; k++) s_w[ox][k] = e[k] * inv;
    }
    __syncthreads();

    // ---- Pass 2: weighted gather (x rows are L2/L1-hot) ----
    if (t < 390) {
        int g  = t / 65;                 // 0..5
        int ox = t - g * 65;             // 0..64

        float w[9];
        #pragma unroll
        for (int k = 0; k < 9; k++) w[k] = s_w[ox][k];

        // column pads
        int cb = 2 * ox - 2;             // float2 base (taps j=0,1), 8B aligned
        int cs = 2 * ox;                 // scalar (tap j=2)
        if (ox == 0)      { cb = 0;     w[0] = w[1] = 0.f; w[3] = w[4] = 0.f; w[6] = w[7] = 0.f; }
        if (ox == OW - 1) { cs = W - 1; w[2] = w[5] = w[8] = 0.f; }

        // row pads
        int iycl[3];
        #pragma unroll
        for (int i = 0; i < 3; i++) {
            int iy = iy0 + i;
            if (iy < 0)       { iy = 0;     w[i*3] = w[i*3+1] = w[i*3+2] = 0.f; }
            else if (iy >= H) { iy = H - 1; w[i*3] = w[i*3+1] = w[i*3+2] = 0.f; }
            iycl[i] = iy;
        }

        const float* xb = x + (size_t)b * C * HW;
        int r0 = iycl[0] * W, r1 = iycl[1] * W, r2 = iycl[2] * W;

        #pragma unroll 2
        for (int c = g; c < C; c += 6) {
            const float* p = xb + (size_t)c * HW;
            float2 a0 = *(const float2*)(p + r0 + cb);
            float2 a1 = *(const float2*)(p + r1 + cb);
            float2 a2 = *(const float2*)(p + r2 + cb);
            float  s0 = p[r0 + cs];
            float  s1 = p[r1 + cs];
            float  s2 = p[r2 + cs];

            float acc;
            acc = w[0] * a0.x;
            acc = fmaf(w[1], a0.y, acc);
            acc = fmaf(w[2], s0,   acc);
            acc = fmaf(w[3], a1.x, acc);
            acc = fmaf(w[4], a1.y, acc);
            acc = fmaf(w[5], s1,   acc);
            acc = fmaf(w[6], a2.x, acc);
            acc = fmaf(w[7], a2.y, acc);
            acc = fmaf(w[8], s2,   acc);

            out[((size_t)(b * C + c) * OH + oy) * OW + ox] = acc;
        }
    }
}

// ---------------------------------------------------------------------------
extern "C" void kernel_launch(void* const* d_in, const int* in_sizes, int n_in,
                              void* d_out, int out_size) {
    const float* x = (const float*)d_in[0];
    float* out = (float*)d_out;

    fused_kernel<<<B * OH, 416>>>(x, out);   // 520 blocks
}

// round 10
// speedup vs baseline: 1.2714x; 1.2714x over previous
#include <cuda_runtime.h>
#include <math.h>

#define B 8
#define C 256
#define H 128
#define W 128
#define OH 65
#define OW 65
#define HW (H*W)          // 16384
#define OHW (OH*OW)       // 4225
#define NPIX (B*OHW)      // 33800
#define SPLIT 8           // channel splits in norm kernel
#define CPS (C/SPLIT)     // 32 channels per split
#define CSPLIT 2          // channel halves in gather
#define CPW 16            // channels per warp in gather (8 warps * 16 * 2 = 256)

// Scratch: device globals
__device__ float g_part[SPLIT*B*HW];     // 4 MB
__device__ float g_norm[B*HW];           // 512 KB
__device__ float g_wts[9*NPIX];          // ~1.22 MB, layout [k][pixel]

// ---------------------------------------------------------------------------
// Kernel 1: partial channel sum-of-squares (proven 7.9 TB/s config).
// ---------------------------------------------------------------------------
__global__ __launch_bounds__(128) void norm_part_kernel(const float* __restrict__ x) {
    int t   = threadIdx.x;
    int w4  = t & 31;
    int hl  = t >> 5;
    int bh4 = blockIdx.x;
    int b   = bh4 >> 5;
    int h   = ((bh4 & 31) << 2) + hl;
    int c0  = blockIdx.y * CPS;

    const float4* p = (const float4*)(x + ((size_t)(b * C + c0)) * HW + (size_t)h * W) + w4;

    float sx = 0.f, sy = 0.f, sz = 0.f, sw = 0.f;
    #pragma unroll 8
    for (int c = 0; c < CPS; c++) {
        float4 v = p[(size_t)c * (HW / 4)];
        sx = fmaf(v.x, v.x, sx);
        sy = fmaf(v.y, v.y, sy);
        sz = fmaf(v.z, v.z, sz);
        sw = fmaf(v.w, v.w, sw);
    }

    float4 o = make_float4(sx, sy, sz, sw);
    ((float4*)g_part)[(size_t)blockIdx.y * (B * HW / 4) + ((size_t)(b * H + h) * W) / 4 + w4] = o;
}

// ---------------------------------------------------------------------------
// Kernel 2: reduce partials + sqrt -> g_norm.
// ---------------------------------------------------------------------------
__global__ __launch_bounds__(256) void norm_reduce_kernel() {
    int i = blockIdx.x * blockDim.x + threadIdx.x;
    if (i >= B * HW / 4) return;
    const float4* p = (const float4*)g_part;
    float4 a = p[i];
    #pragma unroll
    for (int s = 1; s < SPLIT; s++) {
        float4 v = p[(size_t)s * (B * HW / 4) + i];
        a.x += v.x; a.y += v.y; a.z += v.z; a.w += v.w;
    }
    a.x = sqrtf(a.x); a.y = sqrtf(a.y); a.z = sqrtf(a.z); a.w = sqrtf(a.w);
    ((float4*)g_norm)[i] = a;
}

// ---------------------------------------------------------------------------
// Kernel 3: softmax weights, layout [k][pixel].
// ---------------------------------------------------------------------------
__global__ __launch_bounds__(256) void wts_kernel() {
    int idx = blockIdx.x * blockDim.x + threadIdx.x;
    if (idx >= NPIX) return;
    int ox = idx % OW;
    int t  = idx / OW;
    int oy = t % OH;
    int b  = t / OH;

    int iy0 = 2 * oy - 2;
    int ix0 = 2 * ox - 2;

    float v[9];
    #pragma unroll
    for (int i = 0; i < 3; i++) {
        int iy = iy0 + i;
        bool rok = (unsigned)iy < (unsigned)H;
        #pragma unroll
        for (int j = 0; j < 3; j++) {
            int ix = ix0 + j;
            bool ok = rok && ((unsigned)ix < (unsigned)W);
            v[i * 3 + j] = ok ? g_norm[(b * H + iy) * W + ix] : 0.f;
        }
    }

    float m = v[0];
    #pragma unroll
    for (int k = 1; k < 9; k++) m = fmaxf(m, v[k]);

    float e[9], sum = 0.f;
    #pragma unroll
    for (int k = 0; k < 9; k++) { e[k] = expf(v[k] - m); sum += e[k]; }
    float inv = 1.f / sum;

    #pragma unroll
    for (int k = 0; k < 9; k++) g_wts[k * NPIX + idx] = e[k] * inv;
}

// ---------------------------------------------------------------------------
// Kernel 4: register-stencil gather. Block = (b, channel-half, oy), 256 thr.
// Warp owns full 128-col rows: one dense float4/lane load per (channel,row),
// neighbors via shfl_up. Lane l -> ox=2l,2l+1; lane 31 also ox=64.
// ---------------------------------------------------------------------------
__global__ __launch_bounds__(256) void gather_kernel(const float* __restrict__ x,
                                                     float* __restrict__ out) {
    int bid = blockIdx.x;                 // ((b*CSPLIT+cs)*OH + oy)
    int oy  = bid % OH;
    int t2  = bid / OH;
    int cs  = t2 & (CSPLIT - 1);
    int b   = t2 / CSPLIT;

    int warp = threadIdx.x >> 5;
    int lane = threadIdx.x & 31;

    // ---- Weights for this thread's pixels ----
    int pixb = (b * OH + oy) * OW;
    float wA[9], wB[9], wC[9];
    #pragma unroll
    for (int k = 0; k < 9; k++) {
        wA[k] = g_wts[k * NPIX + pixb + 2 * lane];       // ox0 = 2*lane
        wB[k] = g_wts[k * NPIX + pixb + 2 * lane + 1];   // ox1 = 2*lane+1
        wC[k] = g_wts[k * NPIX + pixb + 64];             // ox2 = 64 (lane31 only)
    }

    // Column pads: ox=0 (lane 0): taps j=0,1 are cols -2,-1.
    if (lane == 0) {
        #pragma unroll
        for (int i = 0; i < 3; i++) { wA[i*3+0] = 0.f; wA[i*3+1] = 0.f; }
    }
    // ox=64: tap j=2 is col 128 (pad).
    #pragma unroll
    for (int i = 0; i < 3; i++) wC[i*3+2] = 0.f;

    // Row clamps + pad zeroing.
    int iy0 = 2 * oy - 2;
    int iyv[3];
    #pragma unroll
    for (int i = 0; i < 3; i++) {
        int iy = iy0 + i;
        if (iy < 0 || iy >= H) {
            iy = iy < 0 ? 0 : H - 1;
            wA[i*3] = wA[i*3+1] = wA[i*3+2] = 0.f;
            wB[i*3] = wB[i*3+1] = wB[i*3+2] = 0.f;
            wC[i*3] = wC[i*3+1] = wC[i*3+2] = 0.f;
        }
        iyv[i] = iy;
    }

    const float* xbase = x + (size_t)(b * C + cs * (C / CSPLIT)) * HW;
    float* obase = out + (size_t)(b * C + cs * (C / CSPLIT)) * OHW + (size_t)oy * OW;

    #pragma unroll 4
    for (int ci = 0; ci < CPW; ci++) {
        int c = ci * 8 + warp;            // 0..127 within the half
        const float* rb = xbase + (size_t)c * HW;

        float acc0 = 0.f, acc1 = 0.f, acc2 = 0.f;
        #pragma unroll
        for (int i = 0; i < 3; i++) {
            float4 v = ((const float4*)(rb + iyv[i] * W))[lane];  // cols 4l..4l+3
            float pz = __shfl_up_sync(0xFFFFFFFFu, v.z, 1);       // col 4l-2
            float pw = __shfl_up_sync(0xFFFFFFFFu, v.w, 1);       // col 4l-1

            acc0 = fmaf(wA[i*3+0], pz,  acc0);   // ox0: cols 4l-2,4l-1,4l
            acc0 = fmaf(wA[i*3+1], pw,  acc0);
            acc0 = fmaf(wA[i*3+2], v.x, acc0);
            acc1 = fmaf(wB[i*3+0], v.x, acc1);   // ox1: cols 4l,4l+1,4l+2
            acc1 = fmaf(wB[i*3+1], v.y, acc1);
            acc1 = fmaf(wB[i*3+2], v.z, acc1);
            acc2 = fmaf(wC[i*3+0], v.z, acc2);   // ox=64: cols 126,127 (lane31)
            acc2 = fmaf(wC[i*3+1], v.w, acc2);
        }

        float* orow = obase + (size_t)c * OHW;
        orow[2 * lane]     = acc0;
        orow[2 * lane + 1] = acc1;
        if (lane == 31) orow[64] = acc2;
    }
}

// ---------------------------------------------------------------------------
extern "C" void kernel_launch(void* const* d_in, const int* in_sizes, int n_in,
                              void* d_out, int out_size) {
    const float* x = (const float*)d_in[0];
    float* out = (float*)d_out;

    dim3 g1(B * H / 4, SPLIT);                   // 2048 blocks
    norm_part_kernel<<<g1, 128>>>(x);

    int n2 = B * HW / 4;
    norm_reduce_kernel<<<(n2 + 255) / 256, 256>>>();

    wts_kernel<<<(NPIX + 255) / 256, 256>>>();

    int n4 = B * CSPLIT * OH;                    // 1040 blocks
    gather_kernel<<<n4, 256>>>(x, out);
}